// round 2
// baseline (speedup 1.0000x reference)
#include <cuda_runtime.h>
#include <cuda_fp16.h>
#include <cstdint>

// ============================================================
// out[8192,4096] = x[8192,4096] @ sign(W)[4096,4096]^T + sign(b)
// Harness virtual arch is compute_103 (no 'a'), so tcgen05/TMEM PTX is
// unavailable. Use base-PTX tensor path: cp.async + ldmatrix + mma.sync
// (f16 inputs, f32 accum). sign(W), sign(b) are exact in fp16; x->fp16
// gives ~1.5e-4 aggregate rel error (threshold 1e-3).
// ============================================================

static constexpr int M = 8192;
static constexpr int N = 4096;
static constexpr int K = 4096;

static constexpr int BM = 128;
static constexpr int BN = 128;
static constexpr int BK = 32;
static constexpr int KT = K / BK;          // 128 k-tiles
static constexpr int STAGES = 4;

static constexpr int ROW_HALFS = BK + 8;   // 40 halves = 80B row stride (swizzle pad)
static constexpr int ROW_BYTES = ROW_HALFS * 2;              // 80
static constexpr int TILE_BYTES = BM * ROW_BYTES;            // 10240
static constexpr int STAGE_BYTES = 2 * TILE_BYTES;           // 20480 (A then B)
static constexpr int SMEM_TOTAL = STAGES * STAGE_BYTES;      // 81920

// ---------------- scratch (__device__ globals: alloc-free rule) ------------
__device__ __half g_xh[(size_t)M * K];   // fp16(x)
__device__ __half g_wh[(size_t)N * K];   // fp16(sign(W))
__device__ float  g_bs[N];               // sign(bias)

// ---------------- PTX helpers (base features only) --------------------------
__device__ __forceinline__ uint32_t smem_u32(const void* p) {
    uint32_t a;
    asm("{ .reg .u64 t; cvta.to.shared.u64 t, %1; cvt.u32.u64 %0, t; }"
        : "=r"(a) : "l"(p));
    return a;
}

__device__ __forceinline__ void cp16(uint32_t s, const void* g) {
    asm volatile("cp.async.cg.shared.global [%0], [%1], 16;"
                 :: "r"(s), "l"(g) : "memory");
}
__device__ __forceinline__ void cp_commit() {
    asm volatile("cp.async.commit_group;" ::: "memory");
}
template <int NN>
__device__ __forceinline__ void cp_wait() {
    asm volatile("cp.async.wait_group %0;" :: "n"(NN) : "memory");
}

__device__ __forceinline__ void ldsm4(uint32_t* r, uint32_t addr) {
    asm volatile("ldmatrix.sync.aligned.m8n8.x4.shared.b16 {%0,%1,%2,%3}, [%4];"
                 : "=r"(r[0]), "=r"(r[1]), "=r"(r[2]), "=r"(r[3]) : "r"(addr));
}

__device__ __forceinline__ void mma16816(float* c, const uint32_t* a,
                                         uint32_t b0, uint32_t b1) {
    asm volatile(
        "mma.sync.aligned.m16n8k16.row.col.f32.f16.f16.f32 "
        "{%0,%1,%2,%3}, {%4,%5,%6,%7}, {%8,%9}, {%0,%1,%2,%3};"
        : "+f"(c[0]), "+f"(c[1]), "+f"(c[2]), "+f"(c[3])
        : "r"(a[0]), "r"(a[1]), "r"(a[2]), "r"(a[3]), "r"(b0), "r"(b1));
}

// ---------------- prep: fp32 -> fp16 / sign ---------------------------------
__device__ __forceinline__ float fsign(float v) {
    return (v > 0.f) ? 1.f : ((v < 0.f) ? -1.f : 0.f);
}

__global__ void prep_kernel(const float* __restrict__ x,
                            const float* __restrict__ w,
                            const float* __restrict__ b) {
    const long tid = (long)blockIdx.x * blockDim.x + threadIdx.x;
    const long stride = (long)gridDim.x * blockDim.x;
    const long NX4 = ((long)M * K) / 4;
    const long NW4 = ((long)N * K) / 4;

    __half2* xh2 = reinterpret_cast<__half2*>(g_xh);
    __half2* wh2 = reinterpret_cast<__half2*>(g_wh);

    for (long t = tid; t < NX4; t += stride) {
        float4 v = reinterpret_cast<const float4*>(x)[t];
        xh2[2 * t + 0] = __floats2half2_rn(v.x, v.y);
        xh2[2 * t + 1] = __floats2half2_rn(v.z, v.w);
    }
    for (long t = tid; t < NW4; t += stride) {
        float4 v = reinterpret_cast<const float4*>(w)[t];
        wh2[2 * t + 0] = __floats2half2_rn(fsign(v.x), fsign(v.y));
        wh2[2 * t + 1] = __floats2half2_rn(fsign(v.z), fsign(v.w));
    }
    if (tid < N) g_bs[tid] = fsign(b[tid]);
}

// ---------------- GEMM -------------------------------------------------------
// grid (N/BN=32, M/BM=64), 256 threads (8 warps: 2 m x 4 n), warp tile 64x32.
// 4-stage cp.async pipeline. Smem tiles row-padded to 80B for conflict-free
// ldmatrix (16B-group sequence 0,5,2,7,4,1,6,3 across 8 rows).
__global__ void __launch_bounds__(256, 2)
gemm_kernel(float* __restrict__ out) {
    extern __shared__ __half smem[];
    const uint32_t sbase = smem_u32(smem);

    const int tid = threadIdx.x;
    const int wid = tid >> 5;
    const int lane = tid & 31;
    const int warp_m = wid >> 2;        // 0..1
    const int warp_n = wid & 3;         // 0..3

    const int bn = blockIdx.x;          // 0..31
    const int bm = blockIdx.y;          // 0..63

    const __half* gA = g_xh + (size_t)(bm * BM) * K;
    const __half* gB = g_wh + (size_t)(bn * BN) * K;

    // cp.async chunk mapping: 512 chunks of 16B per tile, 2 per thread.
    const int c0 = tid;                 // chunks c0, c0+256
    // ldmatrix per-lane bases
    const int rowA = warp_m * 64 + (lane & 15);
    const int kbA  = (lane >> 4) * 8;                        // halves
    const int rowB = warp_n * 32 + (lane & 7) + (lane >> 4) * 8;
    const int kbB  = ((lane >> 3) & 1) * 8;                  // halves

    float acc[4][4][4];
    #pragma unroll
    for (int i = 0; i < 4; i++)
        #pragma unroll
        for (int j = 0; j < 4; j++)
            #pragma unroll
            for (int e = 0; e < 4; e++) acc[i][j][e] = 0.f;

    auto issue_stage = [&](int kt) {
        const uint32_t sA = sbase + (kt & (STAGES - 1)) * STAGE_BYTES;
        const uint32_t sB = sA + TILE_BYTES;
        #pragma unroll
        for (int i = 0; i < 2; i++) {
            const int c = c0 + i * 256;
            const int row = c >> 2;
            const int kc = c & 3;
            cp16(sA + row * ROW_BYTES + kc * 16,
                 gA + (size_t)row * K + kt * BK + kc * 8);
            cp16(sB + row * ROW_BYTES + kc * 16,
                 gB + (size_t)row * K + kt * BK + kc * 8);
        }
        cp_commit();
    };

    // prologue: fill 3 stages
    issue_stage(0);
    issue_stage(1);
    issue_stage(2);

    for (int kt = 0; kt < KT; kt++) {
        cp_wait<STAGES - 2>();          // stage kt resident
        __syncthreads();                // everyone done with stage kt-1 too

        if (kt + 3 < KT) issue_stage(kt + 3);
        else cp_commit();               // keep group count aligned

        const uint32_t sA = sbase + (kt & (STAGES - 1)) * STAGE_BYTES;
        const uint32_t sB = sA + TILE_BYTES;

        #pragma unroll
        for (int kk = 0; kk < 2; kk++) {
            uint32_t a[4][4];
            #pragma unroll
            for (int im = 0; im < 4; im++)
                ldsm4(a[im], sA + (rowA + im * 16) * ROW_BYTES
                                + (kbA + kk * 16) * 2);
            uint32_t b[2][4];
            #pragma unroll
            for (int in = 0; in < 2; in++)
                ldsm4(b[in], sB + (rowB + in * 16) * ROW_BYTES
                                + (kbB + kk * 16) * 2);
            #pragma unroll
            for (int im = 0; im < 4; im++)
                #pragma unroll
                for (int jn = 0; jn < 4; jn++)
                    mma16816(acc[im][jn],
                             a[im], b[jn >> 1][(jn & 1) * 2],
                                    b[jn >> 1][(jn & 1) * 2 + 1]);
        }
    }

    // ---------------- epilogue: add sign(bias), store fp32 ------------------
    const int col0 = bn * BN + warp_n * 32 + 2 * (lane & 3);
    const int row0 = bm * BM + warp_m * 64 + (lane >> 2);
    #pragma unroll
    for (int jn = 0; jn < 4; jn++) {
        const int c = col0 + jn * 8;
        const float b0 = g_bs[c];
        const float b1 = g_bs[c + 1];
        #pragma unroll
        for (int im = 0; im < 4; im++) {
            const int r = row0 + im * 16;
            float2 v0 = make_float2(acc[im][jn][0] + b0, acc[im][jn][1] + b1);
            float2 v1 = make_float2(acc[im][jn][2] + b0, acc[im][jn][3] + b1);
            *reinterpret_cast<float2*>(out + (size_t)r * N + c) = v0;
            *reinterpret_cast<float2*>(out + (size_t)(r + 8) * N + c) = v1;
        }
    }
}

// ---------------- host launch ------------------------------------------------
extern "C" void kernel_launch(void* const* d_in, const int* in_sizes, int n_in,
                              void* d_out, int out_size) {
    const float* x = (const float*)d_in[0];
    const float* w = (const float*)d_in[1];
    const float* b = (const float*)d_in[2];
    float* out = (float*)d_out;

    cudaFuncSetAttribute(gemm_kernel, cudaFuncAttributeMaxDynamicSharedMemorySize,
                         SMEM_TOTAL);

    prep_kernel<<<1024, 256>>>(x, w, b);

    dim3 grid(N / BN, M / BM);   // (32, 64)
    gemm_kernel<<<grid, 256, SMEM_TOTAL>>>(out);
}

// round 3
// speedup vs baseline: 1.1858x; 1.1858x over previous
#include <cuda_runtime.h>
#include <cuda_fp16.h>
#include <cstdint>

// ============================================================
// out[8192,4096] = x[8192,4096] @ sign(W)[4096,4096]^T + sign(b)
// Base-PTX tensor path (virtual arch compute_103 rejects tcgen05):
// cp.async + ldmatrix + mma.sync.m16n8k16.f32.f16.
// R3: warp tile 64x64, 4-warp CTA (128 thr), 2 CTAs/SM.
// ============================================================

static constexpr int M = 8192;
static constexpr int N = 4096;
static constexpr int K = 4096;

static constexpr int BM = 128;
static constexpr int BN = 128;
static constexpr int BK = 32;
static constexpr int KT = K / BK;          // 128 k-tiles
static constexpr int STAGES = 4;

static constexpr int ROW_HALFS = BK + 8;   // 40 halves = 80B row stride (pad)
static constexpr int ROW_BYTES = ROW_HALFS * 2;              // 80
static constexpr int TILE_BYTES = BM * ROW_BYTES;            // 10240
static constexpr int STAGE_BYTES = 2 * TILE_BYTES;           // 20480 (A then B)
static constexpr int SMEM_TOTAL = STAGES * STAGE_BYTES;      // 81920

// ---------------- scratch (__device__ globals: alloc-free rule) ------------
__device__ __half g_xh[(size_t)M * K];   // fp16(x)
__device__ __half g_wh[(size_t)N * K];   // fp16(sign(W))
__device__ float  g_bs[N];               // sign(bias)

// ---------------- PTX helpers -----------------------------------------------
__device__ __forceinline__ uint32_t smem_u32(const void* p) {
    uint32_t a;
    asm("{ .reg .u64 t; cvta.to.shared.u64 t, %1; cvt.u32.u64 %0, t; }"
        : "=r"(a) : "l"(p));
    return a;
}

__device__ __forceinline__ void cp16(uint32_t s, const void* g) {
    asm volatile("cp.async.cg.shared.global [%0], [%1], 16;"
                 :: "r"(s), "l"(g) : "memory");
}
__device__ __forceinline__ void cp_commit() {
    asm volatile("cp.async.commit_group;" ::: "memory");
}
template <int NN>
__device__ __forceinline__ void cp_wait() {
    asm volatile("cp.async.wait_group %0;" :: "n"(NN) : "memory");
}

__device__ __forceinline__ void ldsm4(uint32_t* r, uint32_t addr) {
    asm volatile("ldmatrix.sync.aligned.m8n8.x4.shared.b16 {%0,%1,%2,%3}, [%4];"
                 : "=r"(r[0]), "=r"(r[1]), "=r"(r[2]), "=r"(r[3]) : "r"(addr));
}

__device__ __forceinline__ void mma16816(float* c, const uint32_t* a,
                                         uint32_t b0, uint32_t b1) {
    asm volatile(
        "mma.sync.aligned.m16n8k16.row.col.f32.f16.f16.f32 "
        "{%0,%1,%2,%3}, {%4,%5,%6,%7}, {%8,%9}, {%0,%1,%2,%3};"
        : "+f"(c[0]), "+f"(c[1]), "+f"(c[2]), "+f"(c[3])
        : "r"(a[0]), "r"(a[1]), "r"(a[2]), "r"(a[3]), "r"(b0), "r"(b1));
}

// ---------------- prep: fp32 -> fp16 / sign ---------------------------------
__device__ __forceinline__ float fsign(float v) {
    return (v > 0.f) ? 1.f : ((v < 0.f) ? -1.f : 0.f);
}

__global__ void prep_kernel(const float* __restrict__ x,
                            const float* __restrict__ w,
                            const float* __restrict__ b) {
    const long tid = (long)blockIdx.x * blockDim.x + threadIdx.x;
    const long stride = (long)gridDim.x * blockDim.x;
    const long NX4 = ((long)M * K) / 4;
    const long NW4 = ((long)N * K) / 4;

    __half2* xh2 = reinterpret_cast<__half2*>(g_xh);
    __half2* wh2 = reinterpret_cast<__half2*>(g_wh);

    for (long t = tid; t < NX4; t += stride) {
        float4 v = reinterpret_cast<const float4*>(x)[t];
        xh2[2 * t + 0] = __floats2half2_rn(v.x, v.y);
        xh2[2 * t + 1] = __floats2half2_rn(v.z, v.w);
    }
    for (long t = tid; t < NW4; t += stride) {
        float4 v = reinterpret_cast<const float4*>(w)[t];
        wh2[2 * t + 0] = __floats2half2_rn(fsign(v.x), fsign(v.y));
        wh2[2 * t + 1] = __floats2half2_rn(fsign(v.z), fsign(v.w));
    }
    if (tid < N) g_bs[tid] = fsign(b[tid]);
}

// ---------------- GEMM -------------------------------------------------------
// grid (N/BN=32, M/BM=64), 128 threads (4 warps: 2m x 2n), warp tile 64x64.
// 4-stage cp.async pipeline, 2 CTAs/SM.
__global__ void __launch_bounds__(128, 2)
gemm_kernel(float* __restrict__ out) {
    extern __shared__ __half smem[];
    const uint32_t sbase = smem_u32(smem);

    const int tid = threadIdx.x;
    const int wid = tid >> 5;
    const int lane = tid & 31;
    const int warp_m = wid & 1;         // 0..1
    const int warp_n = wid >> 1;        // 0..1

    const int bn = blockIdx.x;          // 0..31
    const int bm = blockIdx.y;          // 0..63

    const __half* gA = g_xh + (size_t)(bm * BM) * K;
    const __half* gB = g_wh + (size_t)(bn * BN) * K;

    // cp.async: 512 chunks of 16B per tile, 4 per thread per tile.
    // ldmatrix per-lane bases
    const int rowA = warp_m * 64 + (lane & 15);
    const int kbA  = (lane >> 4) * 8;                        // halves
    const int rowB = warp_n * 64 + (lane & 7) + (lane >> 4) * 8;
    const int kbB  = ((lane >> 3) & 1) * 8;                  // halves

    float acc[4][8][4];
    #pragma unroll
    for (int i = 0; i < 4; i++)
        #pragma unroll
        for (int j = 0; j < 8; j++)
            #pragma unroll
            for (int e = 0; e < 4; e++) acc[i][j][e] = 0.f;

    auto issue_stage = [&](int kt) {
        const uint32_t sA = sbase + (kt & (STAGES - 1)) * STAGE_BYTES;
        const uint32_t sB = sA + TILE_BYTES;
        #pragma unroll
        for (int i = 0; i < 4; i++) {
            const int c = tid + i * 128;
            const int row = c >> 2;
            const int kc = c & 3;
            const size_t goff = (size_t)row * K + (size_t)kt * BK + kc * 8;
            cp16(sA + row * ROW_BYTES + kc * 16, gA + goff);
            cp16(sB + row * ROW_BYTES + kc * 16, gB + goff);
        }
        cp_commit();
    };

    // prologue: fill 3 stages
    issue_stage(0);
    issue_stage(1);
    issue_stage(2);

    for (int kt = 0; kt < KT; kt++) {
        cp_wait<STAGES - 2>();          // stage kt resident
        __syncthreads();                // stage kt-1 fully consumed

        if (kt + 3 < KT) issue_stage(kt + 3);
        else cp_commit();               // keep group count aligned

        const uint32_t sA = sbase + (kt & (STAGES - 1)) * STAGE_BYTES;
        const uint32_t sB = sA + TILE_BYTES;

        #pragma unroll
        for (int kk = 0; kk < 2; kk++) {
            uint32_t a[4][4];
            #pragma unroll
            for (int im = 0; im < 4; im++)
                ldsm4(a[im], sA + (rowA + im * 16) * ROW_BYTES
                                + (kbA + kk * 16) * 2);
            uint32_t b[4][4];           // b[q] covers n-tiles 2q, 2q+1
            #pragma unroll
            for (int q = 0; q < 4; q++)
                ldsm4(b[q], sB + (rowB + q * 16) * ROW_BYTES
                               + (kbB + kk * 16) * 2);
            #pragma unroll
            for (int im = 0; im < 4; im++)
                #pragma unroll
                for (int jn = 0; jn < 8; jn++)
                    mma16816(acc[im][jn],
                             a[im], b[jn >> 1][(jn & 1) * 2],
                                    b[jn >> 1][(jn & 1) * 2 + 1]);
        }
    }

    // ---------------- epilogue: add sign(bias), store fp32 ------------------
    const int col0 = bn * BN + warp_n * 64 + 2 * (lane & 3);
    const int row0 = bm * BM + warp_m * 64 + (lane >> 2);
    #pragma unroll
    for (int jn = 0; jn < 8; jn++) {
        const int c = col0 + jn * 8;
        const float b0 = g_bs[c];
        const float b1 = g_bs[c + 1];
        #pragma unroll
        for (int im = 0; im < 4; im++) {
            const int r = row0 + im * 16;
            float2 v0 = make_float2(acc[im][jn][0] + b0, acc[im][jn][1] + b1);
            float2 v1 = make_float2(acc[im][jn][2] + b0, acc[im][jn][3] + b1);
            *reinterpret_cast<float2*>(out + (size_t)r * N + c) = v0;
            *reinterpret_cast<float2*>(out + (size_t)(r + 8) * N + c) = v1;
        }
    }
}

// ---------------- host launch ------------------------------------------------
extern "C" void kernel_launch(void* const* d_in, const int* in_sizes, int n_in,
                              void* d_out, int out_size) {
    const float* x = (const float*)d_in[0];
    const float* w = (const float*)d_in[1];
    const float* b = (const float*)d_in[2];
    float* out = (float*)d_out;

    cudaFuncSetAttribute(gemm_kernel, cudaFuncAttributeMaxDynamicSharedMemorySize,
                         SMEM_TOTAL);

    prep_kernel<<<1024, 256>>>(x, w, b);

    dim3 grid(N / BN, M / BM);   // (32, 64)
    gemm_kernel<<<grid, 128, SMEM_TOTAL>>>(out);
}

// round 4
// speedup vs baseline: 1.3016x; 1.0977x over previous
#include <cuda_runtime.h>
#include <cuda_fp16.h>
#include <cstdint>

// ============================================================
// out[8192,4096] = x[8192,4096] @ sign(W)[4096,4096]^T + sign(b)
// Base-PTX tensor path (virtual arch compute_103 rejects tcgen05):
// cp.async + ldmatrix + mma.sync.m16n8k16.f32.f16.
// R4: register-fragment double buffering to hide ldsm->mma latency.
// ============================================================

static constexpr int M = 8192;
static constexpr int N = 4096;
static constexpr int K = 4096;

static constexpr int BM = 128;
static constexpr int BN = 128;
static constexpr int BK = 32;
static constexpr int KT = K / BK;          // 128 k-tiles
static constexpr int STAGES = 4;

static constexpr int ROW_HALFS = BK + 8;   // 40 halves = 80B row stride (pad)
static constexpr int ROW_BYTES = ROW_HALFS * 2;              // 80
static constexpr int TILE_BYTES = BM * ROW_BYTES;            // 10240
static constexpr int STAGE_BYTES = 2 * TILE_BYTES;           // 20480 (A then B)
static constexpr int SMEM_TOTAL = STAGES * STAGE_BYTES;      // 81920

// ---------------- scratch (__device__ globals: alloc-free rule) ------------
__device__ __half g_xh[(size_t)M * K];   // fp16(x)
__device__ __half g_wh[(size_t)N * K];   // fp16(sign(W))
__device__ float  g_bs[N];               // sign(bias)

// ---------------- PTX helpers -----------------------------------------------
__device__ __forceinline__ uint32_t smem_u32(const void* p) {
    uint32_t a;
    asm("{ .reg .u64 t; cvta.to.shared.u64 t, %1; cvt.u32.u64 %0, t; }"
        : "=r"(a) : "l"(p));
    return a;
}

__device__ __forceinline__ void cp16(uint32_t s, const void* g) {
    asm volatile("cp.async.cg.shared.global [%0], [%1], 16;"
                 :: "r"(s), "l"(g) : "memory");
}
__device__ __forceinline__ void cp_commit() {
    asm volatile("cp.async.commit_group;" ::: "memory");
}
template <int NN>
__device__ __forceinline__ void cp_wait() {
    asm volatile("cp.async.wait_group %0;" :: "n"(NN) : "memory");
}

__device__ __forceinline__ void ldsm4(uint32_t* r, uint32_t addr) {
    asm volatile("ldmatrix.sync.aligned.m8n8.x4.shared.b16 {%0,%1,%2,%3}, [%4];"
                 : "=r"(r[0]), "=r"(r[1]), "=r"(r[2]), "=r"(r[3]) : "r"(addr));
}

__device__ __forceinline__ void mma16816(float* c, const uint32_t* a,
                                         uint32_t b0, uint32_t b1) {
    asm volatile(
        "mma.sync.aligned.m16n8k16.row.col.f32.f16.f16.f32 "
        "{%0,%1,%2,%3}, {%4,%5,%6,%7}, {%8,%9}, {%0,%1,%2,%3};"
        : "+f"(c[0]), "+f"(c[1]), "+f"(c[2]), "+f"(c[3])
        : "r"(a[0]), "r"(a[1]), "r"(a[2]), "r"(a[3]), "r"(b0), "r"(b1));
}

// ---------------- prep: fp32 -> fp16 / sign ---------------------------------
__device__ __forceinline__ float fsign(float v) {
    return (v > 0.f) ? 1.f : ((v < 0.f) ? -1.f : 0.f);
}

__global__ void prep_kernel(const float* __restrict__ x,
                            const float* __restrict__ w,
                            const float* __restrict__ b) {
    const long tid = (long)blockIdx.x * blockDim.x + threadIdx.x;
    const long stride = (long)gridDim.x * blockDim.x;
    const long NX4 = ((long)M * K) / 4;
    const long NW4 = ((long)N * K) / 4;

    __half2* xh2 = reinterpret_cast<__half2*>(g_xh);
    __half2* wh2 = reinterpret_cast<__half2*>(g_wh);

    for (long t = tid; t < NX4; t += stride) {
        float4 v = reinterpret_cast<const float4*>(x)[t];
        xh2[2 * t + 0] = __floats2half2_rn(v.x, v.y);
        xh2[2 * t + 1] = __floats2half2_rn(v.z, v.w);
    }
    for (long t = tid; t < NW4; t += stride) {
        float4 v = reinterpret_cast<const float4*>(w)[t];
        wh2[2 * t + 0] = __floats2half2_rn(fsign(v.x), fsign(v.y));
        wh2[2 * t + 1] = __floats2half2_rn(fsign(v.z), fsign(v.w));
    }
    if (tid < N) g_bs[tid] = fsign(b[tid]);
}

// ---------------- GEMM -------------------------------------------------------
// grid (N/BN=32, M/BM=64), 128 threads (4 warps: 2m x 2n), warp tile 64x64.
// 4-stage cp.async smem pipeline + double-buffered register fragments.
__global__ void __launch_bounds__(128, 2)
gemm_kernel(float* __restrict__ out) {
    extern __shared__ __half smem[];
    const uint32_t sbase = smem_u32(smem);

    const int tid = threadIdx.x;
    const int wid = tid >> 5;
    const int lane = tid & 31;
    const int warp_m = wid & 1;         // 0..1
    const int warp_n = wid >> 1;        // 0..1

    const int bn = blockIdx.x;          // 0..31
    const int bm = blockIdx.y;          // 0..63

    const __half* gA = g_xh + (size_t)(bm * BM) * K;
    const __half* gB = g_wh + (size_t)(bn * BN) * K;

    // ldmatrix per-lane bases
    const int rowA = warp_m * 64 + (lane & 15);
    const int kbA  = (lane >> 4) * 8;                        // halves
    const int rowB = warp_n * 64 + (lane & 7) + (lane >> 4) * 8;
    const int kbB  = ((lane >> 3) & 1) * 8;                  // halves

    float acc[4][8][4];
    #pragma unroll
    for (int i = 0; i < 4; i++)
        #pragma unroll
        for (int j = 0; j < 8; j++)
            #pragma unroll
            for (int e = 0; e < 4; e++) acc[i][j][e] = 0.f;

    auto issue_stage = [&](int kt) {
        const uint32_t sA = sbase + (kt & (STAGES - 1)) * STAGE_BYTES;
        const uint32_t sB = sA + TILE_BYTES;
        #pragma unroll
        for (int i = 0; i < 4; i++) {
            const int c = tid + i * 128;
            const int row = c >> 2;
            const int kc = c & 3;
            const size_t goff = (size_t)row * K + (size_t)kt * BK + kc * 8;
            cp16(sA + row * ROW_BYTES + kc * 16, gA + goff);
            cp16(sB + row * ROW_BYTES + kc * 16, gB + goff);
        }
        cp_commit();
    };

    auto load_frags = [&](int stage, int kk, uint32_t (*a)[4], uint32_t (*b)[4]) {
        const uint32_t sA = sbase + stage * STAGE_BYTES;
        const uint32_t sB = sA + TILE_BYTES;
        #pragma unroll
        for (int im = 0; im < 4; im++)
            ldsm4(a[im], sA + (rowA + im * 16) * ROW_BYTES + (kbA + kk * 16) * 2);
        #pragma unroll
        for (int q = 0; q < 4; q++)
            ldsm4(b[q], sB + (rowB + q * 16) * ROW_BYTES + (kbB + kk * 16) * 2);
    };

    auto mma_half = [&](uint32_t (*a)[4], uint32_t (*b)[4]) {
        #pragma unroll
        for (int im = 0; im < 4; im++)
            #pragma unroll
            for (int jn = 0; jn < 8; jn++)
                mma16816(acc[im][jn],
                         a[im], b[jn >> 1][(jn & 1) * 2],
                                b[jn >> 1][(jn & 1) * 2 + 1]);
    };

    uint32_t a0[4][4], b0[4][4], a1[4][4], b1[4][4];

    // prologue: fill 3 stages, land stage 0, preload (kt=0, kk=0) fragments
    issue_stage(0);
    issue_stage(1);
    issue_stage(2);
    cp_wait<2>();
    __syncthreads();
    load_frags(0, 0, a0, b0);

    for (int kt = 0; kt < KT; kt++) {
        const int st  = kt & (STAGES - 1);
        const int stn = (kt + 1 < KT ? kt + 1 : kt) & (STAGES - 1);

        // load (kt, kk1) while kk0 MMAs run
        load_frags(st, 1, a1, b1);
        mma_half(a0, b0);

        // stage kt+1 landed (this thread) + visible to all (barrier);
        // barrier also licenses overwriting buffer (kt-1)&3 below.
        cp_wait<1>();
        __syncthreads();

        // load (kt+1, kk0) while kk1 MMAs run; refill pipeline
        load_frags(stn, 0, a0, b0);
        if (kt + 3 < KT) issue_stage(kt + 3);
        else cp_commit();               // keep group count aligned
        mma_half(a1, b1);
    }

    // ---------------- epilogue: add sign(bias), store fp32 ------------------
    const int col0 = bn * BN + warp_n * 64 + 2 * (lane & 3);
    const int row0 = bm * BM + warp_m * 64 + (lane >> 2);
    #pragma unroll
    for (int jn = 0; jn < 8; jn++) {
        const int c = col0 + jn * 8;
        const float b0v = g_bs[c];
        const float b1v = g_bs[c + 1];
        #pragma unroll
        for (int im = 0; im < 4; im++) {
            const int r = row0 + im * 16;
            float2 v0 = make_float2(acc[im][jn][0] + b0v, acc[im][jn][1] + b1v);
            float2 v1 = make_float2(acc[im][jn][2] + b0v, acc[im][jn][3] + b1v);
            *reinterpret_cast<float2*>(out + (size_t)r * N + c) = v0;
            *reinterpret_cast<float2*>(out + (size_t)(r + 8) * N + c) = v1;
        }
    }
}

// ---------------- host launch ------------------------------------------------
extern "C" void kernel_launch(void* const* d_in, const int* in_sizes, int n_in,
                              void* d_out, int out_size) {
    const float* x = (const float*)d_in[0];
    const float* w = (const float*)d_in[1];
    const float* b = (const float*)d_in[2];
    float* out = (float*)d_out;

    cudaFuncSetAttribute(gemm_kernel, cudaFuncAttributeMaxDynamicSharedMemorySize,
                         SMEM_TOTAL);

    prep_kernel<<<1024, 256>>>(x, w, b);

    dim3 grid(N / BN, M / BM);   // (32, 64)
    gemm_kernel<<<grid, 128, SMEM_TOTAL>>>(out);
}

// round 6
// speedup vs baseline: 1.4005x; 1.0760x over previous
#include <cuda_runtime.h>
#include <cuda_fp16.h>
#include <cstdint>

// ============================================================
// out[8192,4096] = x[8192,4096] @ sign(W)[4096,4096]^T + sign(b)
// Base-PTX tensor path (virtual arch compute_103 rejects tcgen05):
// cp.async + ldmatrix + mma.sync.m16n8k16.f32.f16.
// R6: BK=64 / 3-stage pipeline with FIXED group accounting: next stage
//     is issued BEFORE cp_wait so that cp_wait<1> proves stage kt+1
//     resident (R5's NaN was reading an unlanded stage).
// ============================================================

static constexpr int M = 8192;
static constexpr int N = 4096;
static constexpr int K = 4096;

static constexpr int BM = 128;
static constexpr int BN = 128;
static constexpr int BK = 64;
static constexpr int KT = K / BK;          // 64 k-tiles
static constexpr int STAGES = 3;

static constexpr int ROW_HALFS = BK + 8;   // 72 halves = 144B row (9x16B, conflict-free)
static constexpr int ROW_BYTES = ROW_HALFS * 2;              // 144
static constexpr int TILE_BYTES = BM * ROW_BYTES;            // 18432
static constexpr int STAGE_BYTES = 2 * TILE_BYTES;           // 36864 (A then B)
static constexpr int SMEM_TOTAL = STAGES * STAGE_BYTES;      // 110592

// ---------------- scratch (__device__ globals: alloc-free rule) ------------
__device__ __half g_xh[(size_t)M * K];   // fp16(x)
__device__ __half g_wh[(size_t)N * K];   // fp16(sign(W))
__device__ float  g_bs[N];               // sign(bias)

// ---------------- PTX helpers -----------------------------------------------
__device__ __forceinline__ uint32_t smem_u32(const void* p) {
    uint32_t a;
    asm("{ .reg .u64 t; cvta.to.shared.u64 t, %1; cvt.u32.u64 %0, t; }"
        : "=r"(a) : "l"(p));
    return a;
}

__device__ __forceinline__ void cp16(uint32_t s, const void* g) {
    asm volatile("cp.async.cg.shared.global [%0], [%1], 16;"
                 :: "r"(s), "l"(g) : "memory");
}
__device__ __forceinline__ void cp_commit() {
    asm volatile("cp.async.commit_group;" ::: "memory");
}
template <int NN>
__device__ __forceinline__ void cp_wait() {
    asm volatile("cp.async.wait_group %0;" :: "n"(NN) : "memory");
}

__device__ __forceinline__ void ldsm4(uint32_t* r, uint32_t addr) {
    asm volatile("ldmatrix.sync.aligned.m8n8.x4.shared.b16 {%0,%1,%2,%3}, [%4];"
                 : "=r"(r[0]), "=r"(r[1]), "=r"(r[2]), "=r"(r[3]) : "r"(addr));
}

__device__ __forceinline__ void mma16816(float* c, const uint32_t* a,
                                         uint32_t b0, uint32_t b1) {
    asm volatile(
        "mma.sync.aligned.m16n8k16.row.col.f32.f16.f16.f32 "
        "{%0,%1,%2,%3}, {%4,%5,%6,%7}, {%8,%9}, {%0,%1,%2,%3};"
        : "+f"(c[0]), "+f"(c[1]), "+f"(c[2]), "+f"(c[3])
        : "r"(a[0]), "r"(a[1]), "r"(a[2]), "r"(a[3]), "r"(b0), "r"(b1));
}

// ---------------- prep: fp32 -> fp16 / sign ---------------------------------
__device__ __forceinline__ float fsign(float v) {
    return (v > 0.f) ? 1.f : ((v < 0.f) ? -1.f : 0.f);
}

__global__ void prep_kernel(const float* __restrict__ x,
                            const float* __restrict__ w,
                            const float* __restrict__ b) {
    const long tid = (long)blockIdx.x * blockDim.x + threadIdx.x;
    const long stride = (long)gridDim.x * blockDim.x;
    const long NX4 = ((long)M * K) / 4;
    const long NW4 = ((long)N * K) / 4;

    __half2* xh2 = reinterpret_cast<__half2*>(g_xh);
    __half2* wh2 = reinterpret_cast<__half2*>(g_wh);

    for (long t = tid; t < NX4; t += stride) {
        float4 v = reinterpret_cast<const float4*>(x)[t];
        xh2[2 * t + 0] = __floats2half2_rn(v.x, v.y);
        xh2[2 * t + 1] = __floats2half2_rn(v.z, v.w);
    }
    for (long t = tid; t < NW4; t += stride) {
        float4 v = reinterpret_cast<const float4*>(w)[t];
        wh2[2 * t + 0] = __floats2half2_rn(fsign(v.x), fsign(v.y));
        wh2[2 * t + 1] = __floats2half2_rn(fsign(v.z), fsign(v.w));
    }
    if (tid < N) g_bs[tid] = fsign(b[tid]);
}

// ---------------- GEMM -------------------------------------------------------
// grid (N/BN=32, M/BM=64), 128 threads (4 warps: 2m x 2n), warp tile 64x64.
// 3-stage cp.async pipeline (BK=64) + double-buffered register fragments.
__global__ void __launch_bounds__(128, 2)
gemm_kernel(float* __restrict__ out) {
    extern __shared__ __half smem[];
    const uint32_t sbase = smem_u32(smem);

    const int tid = threadIdx.x;
    const int wid = tid >> 5;
    const int lane = tid & 31;
    const int warp_m = wid & 1;         // 0..1
    const int warp_n = wid >> 1;        // 0..1

    const int bn = blockIdx.x;          // 0..31
    const int bm = blockIdx.y;          // 0..63

    const __half* gA = g_xh + (size_t)(bm * BM) * K;
    const __half* gB = g_wh + (size_t)(bn * BN) * K;

    // ldmatrix per-lane bases
    const int rowA = warp_m * 64 + (lane & 15);
    const int kbA  = (lane >> 4) * 8;                        // halves
    const int rowB = warp_n * 64 + (lane & 7) + (lane >> 4) * 8;
    const int kbB  = ((lane >> 3) & 1) * 8;                  // halves

    float acc[4][8][4];
    #pragma unroll
    for (int i = 0; i < 4; i++)
        #pragma unroll
        for (int j = 0; j < 8; j++)
            #pragma unroll
            for (int e = 0; e < 4; e++) acc[i][j][e] = 0.f;

    auto issue_stage = [&](int kt) {
        const int st = kt % STAGES;
        const uint32_t sA = sbase + st * STAGE_BYTES;
        const uint32_t sB = sA + TILE_BYTES;
        #pragma unroll
        for (int i = 0; i < 8; i++) {
            const int c = tid + i * 128;
            const int row = c >> 3;
            const int kc = c & 7;
            const size_t goff = (size_t)row * K + (size_t)kt * BK + kc * 8;
            cp16(sA + row * ROW_BYTES + kc * 16, gA + goff);
            cp16(sB + row * ROW_BYTES + kc * 16, gB + goff);
        }
        cp_commit();
    };

    auto load_frags = [&](int stage, int kk, uint32_t (*a)[4], uint32_t (*b)[4]) {
        const uint32_t sA = sbase + stage * STAGE_BYTES;
        const uint32_t sB = sA + TILE_BYTES;
        #pragma unroll
        for (int im = 0; im < 4; im++)
            ldsm4(a[im], sA + (rowA + im * 16) * ROW_BYTES + (kbA + kk * 16) * 2);
        #pragma unroll
        for (int q = 0; q < 4; q++)
            ldsm4(b[q], sB + (rowB + q * 16) * ROW_BYTES + (kbB + kk * 16) * 2);
    };

    auto mma_half = [&](uint32_t (*a)[4], uint32_t (*b)[4]) {
        #pragma unroll
        for (int im = 0; im < 4; im++)
            #pragma unroll
            for (int jn = 0; jn < 8; jn++)
                mma16816(acc[im][jn],
                         a[im], b[jn >> 1][(jn & 1) * 2],
                                b[jn >> 1][(jn & 1) * 2 + 1]);
    };

    uint32_t a0[4][4], b0[4][4], a1[4][4], b1[4][4];

    // prologue: fill 2 stages; pending={0,1}, wait<=1 -> stage 0 resident
    issue_stage(0);
    issue_stage(1);
    cp_wait<1>();
    __syncthreads();
    load_frags(0, 0, a0, b0);

    for (int kt = 0; kt < KT; kt++) {
        const int st  = kt % STAGES;
        const int stn = (kt + 1 < KT ? kt + 1 : kt) % STAGES;

        load_frags(st, 1, a1, b1);
        // Issue stage kt+2 NOW (into buffer (kt-1)%3, consumed before the
        // barrier at the end of iteration kt-1 by all threads). This keeps
        // pending groups = {kt+1, kt+2} at the cp_wait below, so wait<=1
        // proves stage kt+1 is resident.
        if (kt + 2 < KT) issue_stage(kt + 2);
        else cp_commit();               // keep group accounting uniform
        mma_half(a0, b0);                   // kk=0

        load_frags(st, 2, a0, b0);
        mma_half(a1, b1);                   // kk=1
        load_frags(st, 3, a1, b1);
        mma_half(a0, b0);                   // kk=2

        // stage kt+1 landed (pending <=1) + visible to all threads; barrier
        // also licenses overwriting buffer (kt)%3 by the issue in iter kt+1.
        cp_wait<1>();
        __syncthreads();

        load_frags(stn, 0, a0, b0);         // next kt, kk=0
        mma_half(a1, b1);                   // kk=3
    }

    // ---------------- epilogue: add sign(bias), store fp32 ------------------
    const int col0 = bn * BN + warp_n * 64 + 2 * (lane & 3);
    const int row0 = bm * BM + warp_m * 64 + (lane >> 2);
    #pragma unroll
    for (int jn = 0; jn < 8; jn++) {
        const int c = col0 + jn * 8;
        const float b0v = g_bs[c];
        const float b1v = g_bs[c + 1];
        #pragma unroll
        for (int im = 0; im < 4; im++) {
            const int r = row0 + im * 16;
            float2 v0 = make_float2(acc[im][jn][0] + b0v, acc[im][jn][1] + b1v);
            float2 v1 = make_float2(acc[im][jn][2] + b0v, acc[im][jn][3] + b1v);
            *reinterpret_cast<float2*>(out + (size_t)r * N + c) = v0;
            *reinterpret_cast<float2*>(out + (size_t)(r + 8) * N + c) = v1;
        }
    }
}

// ---------------- host launch ------------------------------------------------
extern "C" void kernel_launch(void* const* d_in, const int* in_sizes, int n_in,
                              void* d_out, int out_size) {
    const float* x = (const float*)d_in[0];
    const float* w = (const float*)d_in[1];
    const float* b = (const float*)d_in[2];
    float* out = (float*)d_out;

    cudaFuncSetAttribute(gemm_kernel, cudaFuncAttributeMaxDynamicSharedMemorySize,
                         SMEM_TOTAL);

    prep_kernel<<<1024, 256>>>(x, w, b);

    dim3 grid(N / BN, M / BM);   // (32, 64)
    gemm_kernel<<<grid, 128, SMEM_TOTAL>>>(out);
}